// round 15
// baseline (speedup 1.0000x reference)
#include <cuda_runtime.h>
#include <cuda_fp16.h>
#include <stdint.h>
#include <math.h>

// Problem constants (fixed by dataset)
#define Bsz  8
#define Qlen 2048
#define Klen 2048
#define Hdim 128
#define BM   64          // queries per CTA
#define BN   64          // keys per tile
#define NT   128         // 4 warps
#define NTILE (Klen / BN)

#define KTOT (Bsz * Klen * Hdim)   // 2,097,152 elements

// Pre-rounded history (fp16), row-major [b][key][h]; serves as both K (QK) and V (PV)
__device__ __align__(16) __half g_khi[KTOT];

// smem: [0,32K) K double buffer (16KB tiles), [32K,48K) Q-hi, [48K,64K) Q-lo
#define TILE_BYTES 16384
#define QHI_OFF    32768
#define QLO_OFF    49152
#define SMEM_BYTES 65536

#define LOG2E 1.4426950408889634f
#define ONESF16X2 0x3C003C00u     // half2(1.0, 1.0)

__device__ __forceinline__ uint32_t smem_u32(const void* p) {
    uint32_t a;
    asm("{ .reg .u64 t; cvta.to.shared.u64 t, %1; cvt.u32.u64 %0, t; }" : "=r"(a) : "l"(p));
    return a;
}
__device__ __forceinline__ uint32_t h2u(__half2 h) { return *reinterpret_cast<uint32_t*>(&h); }
__device__ __forceinline__ float ex2f(float x) {
    float y; asm("ex2.approx.ftz.f32 %0, %1;" : "=f"(y) : "f"(x)); return y;
}
__device__ __forceinline__ uint32_t ex2h2(uint32_t x) {
    uint32_t y; asm("ex2.approx.f16x2 %0, %1;" : "=r"(y) : "r"(x)); return y;
}

// fp32 pair -> fp16 hi + fp16 residual(lo), packed half2
__device__ __forceinline__ void split_h2(float x, float y, uint32_t& hi, uint32_t& lo) {
    __half2 h = __floats2half2_rn(x, y);
    float rx = x - __half2float(__low2half(h));
    float ry = y - __half2float(__high2half(h));
    __half2 l = __floats2half2_rn(rx, ry);
    hi = h2u(h); lo = h2u(l);
}

// XOR-swizzled tile offset (16B chunks): row in [0,64), bytecol in [0,256)
__device__ __forceinline__ uint32_t swz2(int row, int bytecol) {
    int ch = bytecol >> 4;
    int chs = (ch & 8) | ((ch ^ row) & 7);
    return (uint32_t)(row * 256 + (chs << 4));
}

__device__ __forceinline__ void cpa16(uint32_t dst, const void* src) {
    asm volatile("cp.async.cg.shared.global [%0], [%1], 16;" :: "r"(dst), "l"(src));
}
#define CP_COMMIT() asm volatile("cp.async.commit_group;" ::: "memory")
#define CP_WAIT0()  asm volatile("cp.async.wait_group 0;" ::: "memory")

__device__ __forceinline__ void ldsm_x4(uint32_t& r0, uint32_t& r1, uint32_t& r2, uint32_t& r3,
                                        uint32_t addr) {
    asm volatile("ldmatrix.sync.aligned.m8n8.x4.shared.b16 {%0,%1,%2,%3}, [%4];"
                 : "=r"(r0), "=r"(r1), "=r"(r2), "=r"(r3) : "r"(addr));
}
__device__ __forceinline__ void ldsm_x4_t(uint32_t& r0, uint32_t& r1, uint32_t& r2, uint32_t& r3,
                                          uint32_t addr) {
    asm volatile("ldmatrix.sync.aligned.m8n8.x4.trans.shared.b16 {%0,%1,%2,%3}, [%4];"
                 : "=r"(r0), "=r"(r1), "=r"(r2), "=r"(r3) : "r"(addr));
}
// D(16x8,f32) += A(16x16,f16) * B(16x8,f16)
__device__ __forceinline__ void mma16816(float* d, const uint32_t* a, uint32_t b0, uint32_t b1) {
    asm volatile("mma.sync.aligned.m16n8k16.row.col.f32.f16.f16.f32 "
                 "{%0,%1,%2,%3}, {%4,%5,%6,%7}, {%8,%9}, {%0,%1,%2,%3};"
                 : "+f"(d[0]), "+f"(d[1]), "+f"(d[2]), "+f"(d[3])
                 : "r"(a[0]), "r"(a[1]), "r"(a[2]), "r"(a[3]), "r"(b0), "r"(b1));
}

// ---------------- Pre-pass: round history fp32 -> fp16 ----------------
__global__ __launch_bounds__(256)
void prep_round(const float* __restrict__ history)
{
    const size_t i = ((size_t)blockIdx.x * 256 + threadIdx.x) * 8;
    float4 a = *(const float4*)(history + i);
    float4 b = *(const float4*)(history + i + 4);
    uint32_t h[4];
    h[0] = h2u(__floats2half2_rn(a.x, a.y));
    h[1] = h2u(__floats2half2_rn(a.z, a.w));
    h[2] = h2u(__floats2half2_rn(b.x, b.y));
    h[3] = h2u(__floats2half2_rn(b.z, b.w));
    *(uint4*)(g_khi + i) = make_uint4(h[0], h[1], h[2], h[3]);
}

// ---------------- Main attention kernel ----------------
__global__ __launch_bounds__(NT, 2)
void attn_hmma(const float* __restrict__ out_state,
               float* __restrict__ out)
{
    extern __shared__ __align__(16) char smb[];
    const uint32_t s_base = smem_u32(smb);

    const int t    = threadIdx.x;
    const int wm   = t >> 5;          // warp id = query-row group
    const int lane = t & 31;
    const int g    = lane >> 2;       // row within fragment group (0..7)
    const int tc   = lane & 3;        // col pair within group
    const int q0   = blockIdx.x * BM;
    const int b    = blockIdx.y;

    const float*  q_g  = out_state + (size_t)b * Qlen * Hdim;
    const __half* khiB = g_khi + (size_t)b * Klen * Hdim;
    float*        o_g  = out + (size_t)b * Qlen * Hdim;

    // ---- Prologue A: cooperative Q -> tanh*log2e -> split hi/lo -> smem ----
    {
        #pragma unroll
        for (int j = 0; j < 16; ++j) {
            const int idx = j * NT + t;       // 0..2047 float4s
            const int row = idx >> 5;         // 0..63
            const int c4  = idx & 31;         // float4 within row
            float4 x = *(const float4*)(q_g + (size_t)(q0 + row) * Hdim + c4 * 4);
            x.x = tanhf(x.x) * LOG2E; x.y = tanhf(x.y) * LOG2E;
            x.z = tanhf(x.z) * LOG2E; x.w = tanhf(x.w) * LOG2E;
            uint32_t h0, l0, h1, l1;
            split_h2(x.x, x.y, h0, l0);
            split_h2(x.z, x.w, h1, l1);
            const uint32_t off = swz2(row, c4 * 8) + ((c4 * 8) & 15);   // 8B slot
            *(uint2*)(smb + QHI_OFF + off) = make_uint2(h0, h1);
            *(uint2*)(smb + QLO_OFF + off) = make_uint2(l0, l1);
        }
    }
    __syncthreads();

    // ---- Prologue B: Q-hi A-fragments (kept in regs); Q-lo stays in smem ----
    const int arow = wm * 16 + ((lane >> 3) & 1) * 8 + (lane & 7);
    const int acol = (lane >> 4) * 16;        // byte offset of k-half
    uint32_t qhi[8][4];
    #pragma unroll
    for (int kk = 0; kk < 8; ++kk)
        ldsm_x4(qhi[kk][0], qhi[kk][1], qhi[kk][2], qhi[kk][3],
                s_base + QHI_OFF + swz2(arow, kk * 32 + acol));

    // O accumulator + l column
    float o[16][4];
    #pragma unroll
    for (int n = 0; n < 16; ++n)
        #pragma unroll
        for (int j = 0; j < 4; ++j) o[n][j] = 0.f;
    float ol[4] = {0.f, 0.f, 0.f, 0.f};

    float m0 = -INFINITY, m1 = -INFINITY;

    // ---- Prefetch tile 0 ----
    {
        #pragma unroll
        for (int j = 0; j < 8; ++j) {
            const int idx = j * NT + t;        // 0..1023
            const int row = idx >> 4;
            const int ch  = idx & 15;
            cpa16(s_base + swz2(row, ch << 4), khiB + (size_t)row * Hdim + ch * 8);
        }
        CP_COMMIT();
    }

    for (int kt = 0; kt < NTILE; ++kt) {
        CP_WAIT0();
        __syncthreads();   // tile kt visible; all warps done with the other buffer

        if (kt + 1 < NTILE) {
            const uint32_t sb = s_base + ((kt + 1) & 1) * TILE_BYTES;
            const __half* srcH = khiB + (size_t)(kt + 1) * BN * Hdim;
            #pragma unroll
            for (int j = 0; j < 8; ++j) {
                const int idx = j * NT + t;
                const int row = idx >> 4;
                const int ch  = idx & 15;
                cpa16(sb + swz2(row, ch << 4), srcH + (size_t)row * Hdim + ch * 8);
            }
            CP_COMMIT();
        }

        const uint32_t s_hi = s_base + (kt & 1) * TILE_BYTES;

        // ---- QK^T: S = (Qhi + Qlo) . Khi — register double-buffered fragments ----
        float s[8][4];
        #pragma unroll
        for (int n = 0; n < 8; ++n)
            #pragma unroll
            for (int j = 0; j < 4; ++j) s[n][j] = 0.f;

        uint32_t bh[2][4][4];   // B fragments, ping-pong
        uint32_t ql[2][4];      // Q-lo A fragments, ping-pong

        // preload kk=0 fragments
        #pragma unroll
        for (int np = 0; np < 4; ++np) {
            const int row = np * 16 + (lane & 7) + ((lane >> 4) << 3);
            const int col = ((lane >> 3) & 1) * 16;
            ldsm_x4(bh[0][np][0], bh[0][np][1], bh[0][np][2], bh[0][np][3],
                    s_hi + swz2(row, col));
        }
        ldsm_x4(ql[0][0], ql[0][1], ql[0][2], ql[0][3],
                s_base + QLO_OFF + swz2(arow, acol));

        #pragma unroll
        for (int kk = 0; kk < 8; ++kk) {
            const int cur = kk & 1, nxt = cur ^ 1;
            // prefetch kk+1 fragments BEFORE issuing this step's MMAs
            if (kk < 7) {
                #pragma unroll
                for (int np = 0; np < 4; ++np) {
                    const int row = np * 16 + (lane & 7) + ((lane >> 4) << 3);
                    const int col = (kk + 1) * 32 + ((lane >> 3) & 1) * 16;
                    ldsm_x4(bh[nxt][np][0], bh[nxt][np][1], bh[nxt][np][2], bh[nxt][np][3],
                            s_hi + swz2(row, col));
                }
                ldsm_x4(ql[nxt][0], ql[nxt][1], ql[nxt][2], ql[nxt][3],
                        s_base + QLO_OFF + swz2(arow, (kk + 1) * 32 + acol));
            }
            // MMAs consume the PREVIOUSLY loaded fragments (already landed)
            #pragma unroll
            for (int n = 0; n < 8; ++n)
                mma16816(s[n], qhi[kk], bh[cur][n >> 1][(n & 1) * 2],
                                        bh[cur][n >> 1][(n & 1) * 2 + 1]);
            #pragma unroll
            for (int n = 0; n < 8; ++n)
                mma16816(s[n], ql[cur], bh[cur][n >> 1][(n & 1) * 2],
                                        bh[cur][n >> 1][(n & 1) * 2 + 1]);
        }

        // ---- Online max (warp-local); l via ones-MMA ----
        float t0 = -INFINITY, t1 = -INFINITY;
        #pragma unroll
        for (int n = 0; n < 8; ++n) {
            t0 = fmaxf(t0, fmaxf(s[n][0], s[n][1]));
            t1 = fmaxf(t1, fmaxf(s[n][2], s[n][3]));
        }
        t0 = fmaxf(t0, __shfl_xor_sync(0xffffffffu, t0, 1));
        t0 = fmaxf(t0, __shfl_xor_sync(0xffffffffu, t0, 2));
        t1 = fmaxf(t1, __shfl_xor_sync(0xffffffffu, t1, 1));
        t1 = fmaxf(t1, __shfl_xor_sync(0xffffffffu, t1, 2));

        const float mn0 = fmaxf(m0, t0), mn1 = fmaxf(m1, t1);
        const bool updated = (mn0 != m0) | (mn1 != m1);
        const bool any_up  = __any_sync(0xffffffffu, updated);
        const float al0 = ex2f(m0 - mn0), al1 = ex2f(m1 - mn1);
        m0 = mn0; m1 = mn1;

        // ---- p = 2^(s-m) via packed fp16 ex2 -> pa fragments ----
        uint32_t pa[4][4];
        #pragma unroll
        for (int n = 0; n < 8; ++n) {
            uint32_t ua = h2u(__floats2half2_rn(s[n][0] - mn0, s[n][1] - mn0));
            uint32_t ub = h2u(__floats2half2_rn(s[n][2] - mn1, s[n][3] - mn1));
            pa[n >> 1][(n & 1) * 2]     = ex2h2(ua);
            pa[n >> 1][(n & 1) * 2 + 1] = ex2h2(ub);
        }

        if (any_up) {
            #pragma unroll
            for (int n = 0; n < 16; ++n) {
                o[n][0] *= al0; o[n][1] *= al0;
                o[n][2] *= al1; o[n][3] *= al1;
            }
            ol[0] *= al0; ol[1] *= al0; ol[2] *= al1; ol[3] *= al1;
        }

        // ---- PV: register double-buffered V fragments (ldsm.trans) ----
        {
            uint32_t vr[2][4];
            // preload idx 0 (kg=0, hp=0)
            {
                const int row = (lane & 7) + (((lane >> 3) & 1) << 3);
                const int col = ((lane >> 4) & 1) * 16;
                ldsm_x4_t(vr[0][0], vr[0][1], vr[0][2], vr[0][3], s_hi + swz2(row, col));
            }
            #pragma unroll
            for (int idx = 0; idx < 32; ++idx) {
                const int cur = idx & 1, nxt = cur ^ 1;
                const int kg = idx >> 3, hp = idx & 7;
                if (idx < 31) {
                    const int kg1 = (idx + 1) >> 3, hp1 = (idx + 1) & 7;
                    const int row = kg1 * 16 + (lane & 7) + (((lane >> 3) & 1) << 3);
                    const int col = hp1 * 32 + ((lane >> 4) & 1) * 16;
                    ldsm_x4_t(vr[nxt][0], vr[nxt][1], vr[nxt][2], vr[nxt][3],
                              s_hi + swz2(row, col));
                }
                mma16816(o[2*hp],     pa[kg], vr[cur][0], vr[cur][1]);
                mma16816(o[2*hp + 1], pa[kg], vr[cur][2], vr[cur][3]);
                if (hp == 7)
                    mma16816(ol, pa[kg], ONESF16X2, ONESF16X2);   // row sums -> l
            }
        }
    }

    // ---- Epilogue: normalize by l and store ----
    const float inv0 = 1.0f / ol[0];
    const float inv1 = 1.0f / ol[2];
    float* ob = o_g + (size_t)(q0 + wm * 16 + g) * Hdim;
    #pragma unroll
    for (int n = 0; n < 16; ++n) {
        const int h = n * 8 + tc * 2;
        *(float2*)(ob + h)            = make_float2(o[n][0] * inv0, o[n][1] * inv0);
        *(float2*)(ob + 8 * Hdim + h) = make_float2(o[n][2] * inv1, o[n][3] * inv1);
    }
}

extern "C" void kernel_launch(void* const* d_in, const int* in_sizes, int n_in,
                              void* d_out, int out_size)
{
    const float* out_state = (const float*)d_in[0];
    const float* history   = (const float*)d_in[1];
    float*       out       = (float*)d_out;

    // 1) round history fp32 -> fp16
    prep_round<<<KTOT / 8 / 256, 256>>>(history);

    // 2) fused flash attention: 2-pass QK + fp16 PV, register-pipelined fragments
    cudaFuncSetAttribute(attn_hmma, cudaFuncAttributeMaxDynamicSharedMemorySize, SMEM_BYTES);
    dim3 grid(Qlen / BM, Bsz);
    attn_hmma<<<grid, NT, SMEM_BYTES>>>(out_state, out);
}